// round 1
// baseline (speedup 1.0000x reference)
#include <cuda_runtime.h>
#include <cstdint>

// ---------------------------------------------------------------------------
// Problem constants
// ---------------------------------------------------------------------------
#define M_MODES 10
#define N_PHOT  5
#define N_NB    252     // C(10,5)
#define N_B     2002    // C(14,5)
#define BATCH_THREADS 512

// __device__ global scratch (no allocations allowed)
__device__ float2 g_WR1[10][10];
__device__ float2 g_WL1c[10][5];   // WL1[:, IN_MODES]
__device__ float2 g_WRF[10][10];
__device__ float2 g_WLFc[10][5];   // WLF[:, IN_MODES]
__device__ unsigned g_rows_nb[N_NB];      // 5 modes packed 4 bits each
__device__ unsigned g_rows_b[N_B];
__device__ float    g_inv_norm_b[N_B];

// ---------------------------------------------------------------------------
// complex helpers
// ---------------------------------------------------------------------------
__device__ __forceinline__ float2 cmul(float2 a, float2 b) {
    return make_float2(fmaf(a.x, b.x, -a.y * b.y), fmaf(a.x, b.y, a.y * b.x));
}
__device__ __forceinline__ float2 cadd(float2 a, float2 b) {
    return make_float2(a.x + b.x, a.y + b.y);
}

__device__ __forceinline__ long binom(int n, int k) {
    if (k < 0 || n < 0 || k > n) return 0;
    long r = 1;
    for (int i = 1; i <= k; i++) r = r * (n - k + i) / i;
    return r;
}

// ---------------------------------------------------------------------------
// Setup kernel: interferometers + Fock row tables
// grid: 10 blocks x 256 threads. Block 0: meshes. Blocks 1..9: tables.
// ---------------------------------------------------------------------------
__global__ void setup_kernel(const float* __restrict__ ph_l1,
                             const float* __restrict__ ph_r1,
                             const float* __restrict__ ph_lf,
                             const float* __restrict__ ph_rf) {
    if (blockIdx.x == 0) {
        // 4 interferometers x 45 MZIs, each a 2x2 complex T
        __shared__ float2 T[4][45][4];
        int t = threadIdx.x;
        if (t < 180) {
            int g = t / 45, k = t % 45;
            const float* ph = (g == 0) ? ph_l1 : (g == 1) ? ph_r1 : (g == 2) ? ph_lf : ph_rf;
            float t1 = ph[2 * k], t2 = ph[2 * k + 1];
            float s1, c1, s2, c2v;
            sincosf(t1, &s1, &c1);
            sincosf(t2, &s2, &c2v);
            float2 e1 = make_float2(c1, s1), e2 = make_float2(c2v, s2);
            const float s = 0.7071067811865476f;
            float2 B00 = make_float2(s, 0), B01 = make_float2(0, s);
            float2 B10 = make_float2(0, s), B11 = make_float2(s, 0);
            // M1 = diag(e1,1) @ B
            float2 M100 = cmul(e1, B00), M101 = cmul(e1, B01);
            float2 M110 = B10, M111 = B11;
            // M2 = B @ M1
            float2 M200 = cadd(cmul(B00, M100), cmul(B01, M110));
            float2 M201 = cadd(cmul(B00, M101), cmul(B01, M111));
            float2 M210 = cadd(cmul(B10, M100), cmul(B11, M110));
            float2 M211 = cadd(cmul(B10, M101), cmul(B11, M111));
            // T = diag(e2,1) @ M2
            T[g][k][0] = cmul(e2, M200);
            T[g][k][1] = cmul(e2, M201);
            T[g][k][2] = M210;
            T[g][k][3] = M211;
        }
        __syncthreads();
        if (t < 40) {
            int g = t / 10, col = t % 10;
            float2 u[10];
            #pragma unroll
            for (int m = 0; m < 10; m++) u[m] = make_float2(m == col ? 1.f : 0.f, 0.f);
            int k = 0;
            for (int layer = 0; layer < 10; layer++) {
                for (int p = (layer & 1); p < 9; p += 2) {
                    float2 a = u[p], b = u[p + 1];
                    u[p]     = cadd(cmul(T[g][k][0], a), cmul(T[g][k][1], b));
                    u[p + 1] = cadd(cmul(T[g][k][2], a), cmul(T[g][k][3], b));
                    k++;
                }
            }
            if (g == 0) {
                if ((col & 1) == 0)
                    for (int m = 0; m < 10; m++) g_WL1c[m][col >> 1] = u[m];
            } else if (g == 1) {
                for (int m = 0; m < 10; m++) g_WR1[m][col] = u[m];
            } else if (g == 2) {
                if ((col & 1) == 0)
                    for (int m = 0; m < 10; m++) g_WLFc[m][col >> 1] = u[m];
            } else {
                for (int m = 0; m < 10; m++) g_WRF[m][col] = u[m];
            }
        }
    } else {
        int idx = (blockIdx.x - 1) * blockDim.x + threadIdx.x;
        if (idx < N_NB) {
            // unrank lexicographic combination of 10 choose 5
            int r = idx, x = 0;
            unsigned packed = 0;
            for (int pos = 0; pos < 5; pos++) {
                for (;;) {
                    long cnt = binom(9 - x, 4 - pos);
                    if (r < cnt) break;
                    r -= (int)cnt;
                    x++;
                }
                packed |= (unsigned)x << (4 * pos);
                x++;
            }
            g_rows_nb[idx] = packed;
        } else if (idx < N_NB + N_B) {
            // combinations_with_replacement(10,5) == combinations(14,5) via c=r+pos
            int rank = idx - N_NB;
            int r = rank, x = 0;
            int row[5];
            for (int pos = 0; pos < 5; pos++) {
                for (;;) {
                    long cnt = binom(13 - x, 4 - pos);
                    if (r < cnt) break;
                    r -= (int)cnt;
                    x++;
                }
                row[pos] = x - pos;
                x++;
            }
            unsigned packed = 0;
            int cnt_[10];
            #pragma unroll
            for (int m = 0; m < 10; m++) cnt_[m] = 0;
            #pragma unroll
            for (int pos = 0; pos < 5; pos++) {
                packed |= (unsigned)row[pos] << (4 * pos);
                cnt_[row[pos]]++;
            }
            const float fact[6] = {1.f, 1.f, 2.f, 6.f, 24.f, 120.f};
            float norm = 1.f;
            #pragma unroll
            for (int m = 0; m < 10; m++) norm *= fact[cnt_[m]];
            g_rows_b[rank] = packed;
            g_inv_norm_b[rank] = 1.0f / norm;
        }
    }
}

// ---------------------------------------------------------------------------
// Glynn permanent |perm|^2 via Gray-code over the 16 sign vectors.
// V: shared 10x5 effective unitary columns. packed: 5 row indices, 4b each.
// ---------------------------------------------------------------------------
__device__ __forceinline__ float perm_prob(const float2 (*__restrict__ V)[5], unsigned packed) {
    float2 M[5][5];
    #pragma unroll
    for (int i = 0; i < 5; i++) {
        int ri = (packed >> (4 * i)) & 15;
        #pragma unroll
        for (int j = 0; j < 5; j++) M[i][j] = V[ri][j];
    }
    // gray = 0: all deltas +1
    float2 rs[5];
    #pragma unroll
    for (int j = 0; j < 5; j++) {
        rs[j].x = M[0][j].x + M[1][j].x + M[2][j].x + M[3][j].x + M[4][j].x;
        rs[j].y = M[0][j].y + M[1][j].y + M[2][j].y + M[3][j].y + M[4][j].y;
    }
    float sx = 0.f, sy = 0.f;
    #pragma unroll
    for (int g = 0; g < 16; g++) {
        float2 p = cmul(cmul(cmul(cmul(rs[0], rs[1]), rs[2]), rs[3]), rs[4]);
        float sgn = (g & 1) ? -1.f : 1.f;
        sx = fmaf(sgn, p.x, sx);
        sy = fmaf(sgn, p.y, sy);
        if (g < 15) {
            int gc = g ^ (g >> 1);
            int gn = (g + 1) ^ ((g + 1) >> 1);
            int diff = gc ^ gn;                 // single bit, compile-time per g
            int bit = __ffs(diff) - 1;          // 0..3 -> row bit+1 flips
            int i = bit + 1;
            float dlt = (gn & diff) ? -2.f : 2.f;
            #pragma unroll
            for (int j = 0; j < 5; j++) {
                rs[j].x = fmaf(dlt, M[i][j].x, rs[j].x);
                rs[j].y = fmaf(dlt, M[i][j].y, rs[j].y);
            }
        }
    }
    sx *= 0.0625f;
    sy *= 0.0625f;
    return fmaf(sx, sx, sy * sy);
}

// ---------------------------------------------------------------------------
// Fused main kernel: one block per batch element.
// ---------------------------------------------------------------------------
__global__ __launch_bounds__(BATCH_THREADS)
void qc_main(const float* __restrict__ x, const float* __restrict__ Wd,
             const float* __restrict__ bd, const float* __restrict__ Wo,
             const float* __restrict__ bo, float* __restrict__ out) {
    int b = blockIdx.x;
    int t = threadIdx.x;
    int lane = t & 31;
    int w = t >> 5;

    __shared__ float2 sh_eih[10];
    __shared__ float2 sh_V[10][5];
    __shared__ float  sh_e1[N_NB];
    __shared__ float  sh_red[BATCH_THREADS / 32][10];

    // 1. h = (x@Wd + bd)/pi, warp w computes output mode w
    if (w < 10) {
        float acc = 0.f;
        const float* xb = x + b * 784;
        for (int i = lane; i < 784; i += 32) acc = fmaf(xb[i], Wd[i * 10 + w], acc);
        #pragma unroll
        for (int o = 16; o; o >>= 1) acc += __shfl_xor_sync(0xffffffffu, acc, o);
        if (lane == 0) {
            float h = (acc + bd[w]) * 0.3183098861837907f;  // 1/pi
            float s, c;
            sincosf(h, &s, &c);
            sh_eih[w] = make_float2(c, s);
        }
    }
    __syncthreads();

    // 2. V1[m][j] = sum_k WR1[m][k] * e^{ih_k} * WL1c[k][j]
    if (t < 50) {
        int m = t / 5, j = t % 5;
        float2 s = make_float2(0.f, 0.f);
        #pragma unroll
        for (int k = 0; k < 10; k++)
            s = cadd(s, cmul(g_WR1[m][k], cmul(sh_eih[k], g_WL1c[k][j])));
        sh_V[m][j] = s;
    }
    __syncthreads();

    // 3. 252 no-bunching probabilities (norm = 1)
    if (t < N_NB) sh_e1[t] = perm_prob(sh_V, g_rows_nb[t]);
    __syncthreads();

    // 4. phi2[m] = sum_j e1[m + 10j]; then e^{i phi2}
    if (t < 10) {
        float phi = 0.f;
        for (int j2 = t; j2 < N_NB; j2 += 10) phi += sh_e1[j2];
        float s, c;
        sincosf(phi, &s, &c);
        sh_eih[t] = make_float2(c, s);
    }
    __syncthreads();

    // 5. VF[m][j] = sum_k WRF[m][k] * e^{i phi2_k} * WLFc[k][j]
    if (t < 50) {
        int m = t / 5, j = t % 5;
        float2 s = make_float2(0.f, 0.f);
        #pragma unroll
        for (int k = 0; k < 10; k++)
            s = cadd(s, cmul(g_WRF[m][k], cmul(sh_eih[k], g_WLFc[k][j])));
        sh_V[m][j] = s;
    }
    __syncthreads();

    // 6. 2002 bunched probabilities, fused with probs @ W_out
    float acc[10];
    #pragma unroll
    for (int c = 0; c < 10; c++) acc[c] = 0.f;
    for (int k = t; k < N_B; k += BATCH_THREADS) {
        float p = perm_prob(sh_V, g_rows_b[k]) * g_inv_norm_b[k];
        const float* wr = Wo + k * 10;
        #pragma unroll
        for (int c = 0; c < 10; c++) acc[c] = fmaf(p, wr[c], acc[c]);
    }
    #pragma unroll
    for (int c = 0; c < 10; c++) {
        #pragma unroll
        for (int o = 16; o; o >>= 1) acc[c] += __shfl_xor_sync(0xffffffffu, acc[c], o);
    }
    if (lane == 0) {
        #pragma unroll
        for (int c = 0; c < 10; c++) sh_red[w][c] = acc[c];
    }
    __syncthreads();
    if (t < 10) {
        float s = bo[t];
        #pragma unroll
        for (int ww = 0; ww < BATCH_THREADS / 32; ww++) s += sh_red[ww][t];
        out[b * 10 + t] = s;
    }
}

// ---------------------------------------------------------------------------
extern "C" void kernel_launch(void* const* d_in, const int* in_sizes, int n_in,
                              void* d_out, int out_size) {
    const float* x   = (const float*)d_in[0];
    const float* Wd  = (const float*)d_in[1];
    const float* bd  = (const float*)d_in[2];
    const float* pl1 = (const float*)d_in[3];
    const float* pr1 = (const float*)d_in[4];
    const float* plf = (const float*)d_in[5];
    const float* prf = (const float*)d_in[6];
    const float* Wo  = (const float*)d_in[7];
    const float* bo  = (const float*)d_in[8];
    float* out = (float*)d_out;

    int B = in_sizes[0] / 784;

    setup_kernel<<<10, 256>>>(pl1, pr1, plf, prf);
    qc_main<<<B, BATCH_THREADS>>>(x, Wd, bd, Wo, bo, out);
}